// round 15
// baseline (speedup 1.0000x reference)
#include <cuda_runtime.h>
#include <cstdint>

// Problem constants (fixed shapes per setup_inputs)
#define BB     256
#define NN     65536
#define KK     64
#define TILE   256
#define NTILES (NN/TILE)         // 256
#define CSLOTS 64                // candidate slots per (b,k) segment
#define THRF   0.0390625f        // 40/1024 fixed candidate threshold

// ---------------- scratch (device globals; no allocation allowed) ----------
__device__ unsigned int g_key[(size_t)BB*NN]; // key bits, cluster-sorted per row (67MB)
__device__ unsigned long long g_cand[(size_t)BB*KK*CSLOTS]; // candidates (8MB)
__device__ int   g_cnum[BB*KK];    // candidate counts
__device__ int   g_counts[BB*KK];
__device__ int   g_msc[NN];        // (cluster<<16)|neuron at sorted position s
__device__ int   g_starts[KK+1];
__device__ float g_p[KK];
__device__ int   g_hist[NTILES*KK];
__device__ int   g_off [NTILES*KK];

// ---------------- Threefry-2x32 (JAX / Random123 exact) --------------------
// Pipe-balancing add: a + b issued as IMAD (a*one + b) on the FMA pipe.
// `one` is a runtime value (always 1) so it cannot be constant-folded.
__device__ __forceinline__ uint32_t madd(uint32_t a, uint32_t b, uint32_t one) {
    uint32_t r;
    asm("mad.lo.u32 %0, %1, %2, %3;" : "=r"(r) : "r"(a), "r"(one), "r"(b));
    return r;
}

// Fused rotate-left + XOR:
//   rotl(x,d) = lo|hi of the 64-bit product x * 2^d  -> IMAD.WIDE (FMA pipe)
//   (lo | hi) ^ c                                    -> single LOP3 (LUT 0x56)
// Replaces SHF(alu) + LOP3.XOR(alu) with IMAD.WIDE(fma) + LOP3(alu),
// halving the forced-ALU work per cipher round. Bit-exact.
__device__ __forceinline__ uint32_t rotxor(uint32_t x, uint32_t pow2d, uint32_t c) {
    uint64_t p;
    asm("mul.wide.u32 %0, %1, %2;" : "=l"(p) : "r"(x), "r"(pow2d));
    uint32_t lo = (uint32_t)p;
    uint32_t hi = (uint32_t)(p >> 32);
    uint32_t r;
    asm("lop3.b32 %0, %1, %2, %3, 0x56;" : "=r"(r) : "r"(lo), "r"(hi), "r"(c));
    return r;
}

// partitionable random_bits (32-bit): bits(i) = o0 ^ o1 of cipher(key, (0, i)).
// Counter hi word is 0, so x0 starts exactly at k0.
__device__ __forceinline__ uint32_t tf_bits32_d(uint32_t k0, uint32_t k1,
                                                uint32_t ks2, uint32_t one,
                                                uint32_t i) {
    uint32_t x0 = k0;          // 0 + k0
    uint32_t x1 = i + k1;
#define TF_R(d) \
    x0 = madd(x0, x1, one); x1 = rotxor(x1, (1u << (d)), x0);
    TF_R(13) TF_R(15) TF_R(26) TF_R(6)
    x0 += k1;  x1 += ks2 + 1u;
    TF_R(17) TF_R(29) TF_R(16) TF_R(24)
    x0 += ks2; x1 += k0 + 2u;
    TF_R(13) TF_R(15) TF_R(26) TF_R(6)
    x0 += k0;  x1 += k1 + 3u;
    TF_R(17) TF_R(29) TF_R(16) TF_R(24)
    x0 += k1;  x1 += ks2 + 4u;
    TF_R(13) TF_R(15) TF_R(26) TF_R(6)
    x0 += ks2; x1 += k0 + 5u;
#undef TF_R
    return x0 ^ x1;
}

// ---------------- K1: fused softmax*SPARSITY + zeroing + histogram ---------
__global__ void k_prep_hist(const float* __restrict__ w,
                            const int* __restrict__ assign) {
    __shared__ int h[KK];
    int tid = threadIdx.x;
    int blk = blockIdx.x;
    if (blk == 0 && tid == 0) {
        float mx = w[0];
        for (int k = 1; k < KK; k++) mx = fmaxf(mx, w[k]);
        float e[KK];
        float sum = 0.f;
        for (int k = 0; k < KK; k++) { e[k] = expf(w[k] - mx); sum += e[k]; }
        for (int k = 0; k < KK; k++) g_p[k] = __fmul_rn(e[k] / sum, 0.1f);
    }
    // distributed zero of g_counts and g_cnum (BB*KK = 16384 = NTILES*64)
    for (int i = tid; i < (BB*KK)/NTILES; i += TILE) {
        int idx = blk * ((BB*KK)/NTILES) + i;
        g_counts[idx] = 0;
        g_cnum[idx]   = 0;
    }

    if (tid < KK) h[tid] = 0;
    __syncthreads();
    int n = blk * TILE + tid;
    atomicAdd(&h[assign[n]], 1);
    __syncthreads();
    if (tid < KK) g_hist[blk * KK + tid] = h[tid];
}

__global__ void k_scan() {               // launch with KK threads, 1 block
    __shared__ int tot[KK];
    int k = threadIdx.x;
    int s = 0;
    for (int t = 0; t < NTILES; t++) s += g_hist[t*KK + k];
    tot[k] = s;
    __syncthreads();
    int start = 0;
    for (int j = 0; j < k; j++) start += tot[j];
    g_starts[k] = start;
    if (k == 0) g_starts[KK] = NN;
    int run = start;
    for (int t = 0; t < NTILES; t++) { g_off[t*KK + k] = run; run += g_hist[t*KK + k]; }
}

// Stable rank within the tile via warp match + cross-warp histogram prefix.
__global__ void k_scatter(const int* __restrict__ assign) {
    __shared__ int whist[TILE/32][KK];
    int tid  = threadIdx.x;
    int wid  = tid >> 5;
    int lane = tid & 31;
    for (int i = tid; i < (TILE/32)*KK; i += TILE) ((int*)whist)[i] = 0;
    __syncthreads();

    int n = blockIdx.x * TILE + tid;
    int c = assign[n];
    unsigned mask = __match_any_sync(0xffffffffu, c);
    int rank_in_warp = __popc(mask & ((1u << lane) - 1u));
    if (rank_in_warp == 0) whist[wid][c] = __popc(mask);   // leader writes count
    __syncthreads();

    int prefix = 0;
    #pragma unroll
    for (int w = 0; w < TILE/32; w++)
        if (w < wid) prefix += whist[w][c];

    int pos = g_off[blockIdx.x * KK + c] + prefix + rank_in_warp;
    g_msc[pos] = (c << 16) | n;
}

// ---------------- B1: Threefry gen + counts + zero + candidate push --------
// Partitionable threefry: element (b, n), flat index i = b*NN+n (< 2^24, so
// hi word = 0): u = bits(ku, i), v = bits(kv, i). Two sorted positions per
// thread -> 4 independent cipher chains (ILP), uint2/float2 stores.
// Keys with fraction < THRF are pushed as candidates (composite (key,j)+1)
// into the per-(b,k) global buffer; k_select uses them when sufficient.
__device__ __forceinline__ void push_cand(int b, int c, int s, unsigned kb) {
    int seg = b * KK + c;
    int j = s - g_starts[c];
    int slot = atomicAdd(&g_cnum[seg], 1);
    if (slot < CSLOTS)
        g_cand[(size_t)seg * CSLOTS + slot] =
            ((((unsigned long long)kb) << 32) | (unsigned)j) + 1ull;
}

__global__ void __launch_bounds__(256) k_gen(float* __restrict__ out,
                                             uint32_t ku0, uint32_t ku1, uint32_t ksu2,
                                             uint32_t kv0, uint32_t kv1, uint32_t ksv2,
                                             uint32_t one) {
    int s0  = blockIdx.x * 512 + threadIdx.x * 2;      // even
    int b   = blockIdx.y;                              // [0, BB)
    int tid = threadIdx.x;
    __shared__ int sc[KK];
    if (tid < KK) sc[tid] = 0;
    __syncthreads();

    int2 mm = *reinterpret_cast<const int2*>(&g_msc[s0]);
    int nA = mm.x & 0xffff, cA = mm.x >> 16;
    int nB = mm.y & 0xffff, cB = mm.y >> 16;
    uint32_t base = (uint32_t)b * NN;
    uint32_t ctrA = base + (uint32_t)nA;
    uint32_t ctrB = base + (uint32_t)nB;

    // 4 independent cipher chains, interleaved by the compiler for ILP
    uint32_t uA = tf_bits32_d(ku0, ku1, ksu2, one, ctrA);
    uint32_t uB = tf_bits32_d(ku0, ku1, ksu2, one, ctrB);
    uint32_t vA = tf_bits32_d(kv0, kv1, ksv2, one, ctrA);
    uint32_t vB = tf_bits32_d(kv0, kv1, ksv2, one, ctrB);

    float cfA = (float)cA, cfB = (float)cB;
    float fuA = __uint_as_float((uA >> 9) | 0x3f800000u) - 1.0f;
    float fuB = __uint_as_float((uB >> 9) | 0x3f800000u) - 1.0f;
    // key = fl(c + fl(u*0.999f)) : NO fma contraction (matches XLA mul-then-add)
    uint2 kb;
    kb.x = __float_as_uint(__fadd_rn(cfA, __fmul_rn(fuA, 0.999f)));
    kb.y = __float_as_uint(__fadd_rn(cfB, __fmul_rn(fuB, 0.999f)));

    size_t o0 = (size_t)b * NN + s0;
    // Within a cluster segment all keys share the integer part c, so the raw
    // float bits order identically to the float values (all nonnegative).
    *reinterpret_cast<uint2*>(&g_key[o0]) = kb;
    *reinterpret_cast<float2*>(&out[o0])  = make_float2(0.0f, 0.0f);

    // candidate push (~3.9% of elements)
    if (kb.x < __float_as_uint(cfA + THRF)) push_cand(b, cA, s0,     kb.x);
    if (kb.y < __float_as_uint(cfB + THRF)) push_cand(b, cB, s0 + 1, kb.y);

    float fvA = __uint_as_float((vA >> 9) | 0x3f800000u) - 1.0f;
    float fvB = __uint_as_float((vB >> 9) | 0x3f800000u) - 1.0f;
    if (fvA < g_p[cA]) atomicAdd(&sc[cA], 1);   // rare (~p=0.0016)
    if (fvB < g_p[cB]) atomicAdd(&sc[cB], 1);
    __syncthreads();
    if (tid < KK && sc[tid]) atomicAdd(&g_counts[b*KK + tid], sc[tid]);
}

// ---------------- B2: per-(b,k) warp selection of `count` smallest ---------
// Fast path: candidates = ALL segment elements with key fraction < THRF.
// If cnt <= nc <= CSLOTS, the cnt smallest of the segment are necessarily
// all candidates => selecting among candidates is exact. Otherwise fall back
// to full-scan rounds over g_key (deterministic, always correct).
// Stable argsort tie-break: counting sort is stable => position j monotone in
// original index n within a segment; composite (key_bits, j) reproduces it.
__global__ void __launch_bounds__(256) k_select(const float* __restrict__ x,
                                                float* __restrict__ out) {
    int lane = threadIdx.x & 31;
    int gwid = (blockIdx.x * blockDim.x + threadIdx.x) >> 5;
    if (gwid >= BB * KK) return;
    int b = gwid >> 6;
    int k = gwid & 63;

    int st = g_starts[k];
    int sz = g_starts[k+1] - st;
    int cnt = g_counts[b*KK + k];
    if (cnt < 1) cnt = 1;            // counts = max(counts, 1)
    if (cnt > sz) cnt = sz;

    int seg = b * KK + k;
    int nc = g_cnum[seg];

    unsigned long long prev = 0ull;  // composites are >= 1
    if (cnt <= nc && nc <= CSLOTS) {
        const unsigned long long* cand = &g_cand[(size_t)seg * CSLOTS];
        for (int r = 0; r < cnt; r++) {
            unsigned long long best = ~0ull;
            for (int j = lane; j < nc; j += 32) {
                unsigned long long cmp = __ldg(&cand[j]);
                if (cmp > prev && cmp < best) best = cmp;
            }
            #pragma unroll
            for (int o = 16; o; o >>= 1) {
                unsigned long long other = __shfl_xor_sync(0xffffffffu, best, o);
                if (other < best) best = other;
            }
            prev = best;
            if (lane == 0) {
                unsigned int j = (unsigned int)((best - 1ull) & 0xffffffffull);
                int n = g_msc[st + (int)j] & 0xffff;
                size_t idx = (size_t)b * NN + (unsigned)n;
                out[idx] = x[idx];
            }
        }
    } else {
        // fallback: full-scan rounds over the stored keys
        const unsigned int* row = g_key + (size_t)b * NN + st;
        for (int r = 0; r < cnt; r++) {
            unsigned long long best = ~0ull;
            #pragma unroll 4
            for (int j = lane; j < sz; j += 32) {
                unsigned long long cmp =
                    ((((unsigned long long)__ldg(&row[j])) << 32) | (unsigned)j) + 1ull;
                if (cmp > prev && cmp < best) best = cmp;
            }
            #pragma unroll
            for (int o = 16; o; o >>= 1) {
                unsigned long long other = __shfl_xor_sync(0xffffffffu, best, o);
                if (other < best) best = other;
            }
            if (best == ~0ull) break;
            prev = best;
            if (lane == 0) {
                unsigned int j = (unsigned int)((best - 1ull) & 0xffffffffull);
                int n = g_msc[st + (int)j] & 0xffff;
                size_t idx = (size_t)b * NN + (unsigned)n;
                out[idx] = x[idx];
            }
        }
    }
}

// ---------------- host-side threefry for the key split ---------------------
static inline uint32_t h_rotl(uint32_t x, int d) { return (x << d) | (x >> (32 - d)); }
static void h_threefry(uint32_t k0, uint32_t k1, uint32_t x0, uint32_t x1,
                       uint32_t& o0, uint32_t& o1) {
    uint32_t ks2 = k0 ^ k1 ^ 0x1BD11BDAu;
    x0 += k0; x1 += k1;
    static const int ra[4] = {13,15,26,6}, rb[4] = {17,29,16,24};
    const int* rots[5] = {ra, rb, ra, rb, ra};
    const uint32_t xi[5] = {k1, ks2, k0, k1, ks2};
    const uint32_t yi[5] = {ks2, k0, k1, ks2, k0};
    for (int g = 0; g < 5; g++) {
        for (int i = 0; i < 4; i++) {
            x0 += x1; x1 = h_rotl(x1, rots[g][i]); x1 ^= x0;
        }
        x0 += xi[g];
        x1 += yi[g] + (uint32_t)(g + 1);
    }
    o0 = x0; o1 = x1;
}

extern "C" void kernel_launch(void* const* d_in, const int* in_sizes, int n_in,
                              void* d_out, int out_size) {
    const float* x      = (const float*)d_in[0];
    const float* w      = (const float*)d_in[1];
    const int*   assign = (const int*)  d_in[2];
    float* out = (float*)d_out;
    (void)in_sizes; (void)n_in; (void)out_size;

    // jax_threefry_partitionable=True (modern default):
    //   split(key(42)) fold-like: subkey i = full cipher((0,42), (hi=0, lo=i))
    //   ku = cipher(0,42; 0,0), kv = cipher(0,42; 0,1)
    uint32_t ku0, ku1, kv0, kv1;
    h_threefry(0u, 42u, 0u, 0u, ku0, ku1);
    h_threefry(0u, 42u, 0u, 1u, kv0, kv1);
    uint32_t ksu2 = ku0 ^ ku1 ^ 0x1BD11BDAu;
    uint32_t ksv2 = kv0 ^ kv1 ^ 0x1BD11BDAu;

    k_prep_hist<<<NTILES, TILE>>>(w, assign);
    k_scan<<<1, KK>>>();
    k_scatter<<<NTILES, TILE>>>(assign);
    k_gen<<<dim3(NN/512, BB), 256>>>(out, ku0, ku1, ksu2, kv0, kv1, ksv2, 1u);
    k_select<<<(BB*KK)/8, 256>>>(x, out);
}

// round 16
// speedup vs baseline: 1.2535x; 1.2535x over previous
#include <cuda_runtime.h>
#include <cstdint>

// Problem constants (fixed shapes per setup_inputs)
#define BB     256
#define NN     65536
#define KK     64
#define TILE   256
#define NTILES (NN/TILE)         // 256
#define CSLOTS 64                // candidate slots per (b,k) segment
#define THRF   0.0390625f        // 40/1024 fixed candidate threshold

// ---------------- scratch (device globals; no allocation allowed) ----------
__device__ unsigned int g_key[(size_t)BB*NN]; // key bits, cluster-sorted per row (67MB)
__device__ unsigned long long g_cand[(size_t)BB*KK*CSLOTS]; // candidates (8MB)
__device__ int   g_cnum[BB*KK];    // candidate counts
__device__ int   g_counts[BB*KK];
__device__ int   g_msc[NN];        // (cluster<<16)|neuron at sorted position s
__device__ int   g_starts[KK+1];
__device__ float g_p[KK];
__device__ int   g_hist[NTILES*KK];
__device__ int   g_off [NTILES*KK];

// ---------------- Threefry-2x32 (JAX / Random123 exact) --------------------
__device__ __forceinline__ uint32_t rotl_d(uint32_t x, int d) {
    return __funnelshift_l(x, x, d);
}

// Pipe-balancing add: a + b issued as IMAD (a*one + b) on the FMA pipe.
// `one` is a runtime value (always 1) so it cannot be constant-folded.
__device__ __forceinline__ uint32_t madd(uint32_t a, uint32_t b, uint32_t one) {
    uint32_t r;
    asm("mad.lo.u32 %0, %1, %2, %3;" : "=r"(r) : "r"(a), "r"(one), "r"(b));
    return r;
}

// partitionable random_bits (32-bit): bits(i) = o0 ^ o1 of cipher(key, (0, i)).
// Counter hi word is 0, so x0 starts exactly at k0.
__device__ __forceinline__ uint32_t tf_bits32_d(uint32_t k0, uint32_t k1,
                                                uint32_t ks2, uint32_t one,
                                                uint32_t i) {
    uint32_t x0 = k0;          // 0 + k0
    uint32_t x1 = i + k1;
#define TF_R(d) \
    x0 = madd(x0, x1, one); x1 = rotl_d(x1, (d)); x1 ^= x0;
    TF_R(13) TF_R(15) TF_R(26) TF_R(6)
    x0 += k1;  x1 += ks2 + 1u;
    TF_R(17) TF_R(29) TF_R(16) TF_R(24)
    x0 += ks2; x1 += k0 + 2u;
    TF_R(13) TF_R(15) TF_R(26) TF_R(6)
    x0 += k0;  x1 += k1 + 3u;
    TF_R(17) TF_R(29) TF_R(16) TF_R(24)
    x0 += k1;  x1 += ks2 + 4u;
    TF_R(13) TF_R(15) TF_R(26) TF_R(6)
    x0 += ks2; x1 += k0 + 5u;
#undef TF_R
    return x0 ^ x1;
}

// ---------------- K1: fused softmax*SPARSITY + zeroing + histogram ---------
__global__ void k_prep_hist(const float* __restrict__ w,
                            const int* __restrict__ assign) {
    __shared__ int h[KK];
    int tid = threadIdx.x;
    int blk = blockIdx.x;
    if (blk == 0 && tid == 0) {
        float mx = w[0];
        for (int k = 1; k < KK; k++) mx = fmaxf(mx, w[k]);
        float e[KK];
        float sum = 0.f;
        for (int k = 0; k < KK; k++) { e[k] = expf(w[k] - mx); sum += e[k]; }
        for (int k = 0; k < KK; k++) g_p[k] = __fmul_rn(e[k] / sum, 0.1f);
    }
    // distributed zero of g_counts and g_cnum (BB*KK = 16384 = NTILES*64)
    for (int i = tid; i < (BB*KK)/NTILES; i += TILE) {
        int idx = blk * ((BB*KK)/NTILES) + i;
        g_counts[idx] = 0;
        g_cnum[idx]   = 0;
    }

    if (tid < KK) h[tid] = 0;
    __syncthreads();
    int n = blk * TILE + tid;
    atomicAdd(&h[assign[n]], 1);
    __syncthreads();
    if (tid < KK) g_hist[blk * KK + tid] = h[tid];
}

__global__ void k_scan() {               // launch with KK threads, 1 block
    __shared__ int tot[KK];
    int k = threadIdx.x;
    int s = 0;
    for (int t = 0; t < NTILES; t++) s += g_hist[t*KK + k];
    tot[k] = s;
    __syncthreads();
    int start = 0;
    for (int j = 0; j < k; j++) start += tot[j];
    g_starts[k] = start;
    if (k == 0) g_starts[KK] = NN;
    int run = start;
    for (int t = 0; t < NTILES; t++) { g_off[t*KK + k] = run; run += g_hist[t*KK + k]; }
}

// Stable rank within the tile via warp match + cross-warp histogram prefix.
__global__ void k_scatter(const int* __restrict__ assign) {
    __shared__ int whist[TILE/32][KK];
    int tid  = threadIdx.x;
    int wid  = tid >> 5;
    int lane = tid & 31;
    for (int i = tid; i < (TILE/32)*KK; i += TILE) ((int*)whist)[i] = 0;
    __syncthreads();

    int n = blockIdx.x * TILE + tid;
    int c = assign[n];
    unsigned mask = __match_any_sync(0xffffffffu, c);
    int rank_in_warp = __popc(mask & ((1u << lane) - 1u));
    if (rank_in_warp == 0) whist[wid][c] = __popc(mask);   // leader writes count
    __syncthreads();

    int prefix = 0;
    #pragma unroll
    for (int w = 0; w < TILE/32; w++)
        if (w < wid) prefix += whist[w][c];

    int pos = g_off[blockIdx.x * KK + c] + prefix + rank_in_warp;
    g_msc[pos] = (c << 16) | n;
}

// ---------------- B1: Threefry gen + counts + zero + candidate push --------
// Partitionable threefry: element (b, n), flat index i = b*NN+n (< 2^24, so
// hi word = 0): u = bits(ku, i), v = bits(kv, i). FOUR sorted positions per
// thread -> 8 independent cipher chains (deep ILP), int4/uint4/float4
// loads+stores amortize per-element overhead.
// Keys with fraction < THRF are pushed as candidates (composite (key,j)+1)
// into the per-(b,k) global buffer; k_select uses them when sufficient.
__device__ __forceinline__ void push_cand(int b, int c, int s, unsigned kb) {
    int seg = b * KK + c;
    int j = s - g_starts[c];
    int slot = atomicAdd(&g_cnum[seg], 1);
    if (slot < CSLOTS)
        g_cand[(size_t)seg * CSLOTS + slot] =
            ((((unsigned long long)kb) << 32) | (unsigned)j) + 1ull;
}

__global__ void __launch_bounds__(256) k_gen(float* __restrict__ out,
                                             uint32_t ku0, uint32_t ku1, uint32_t ksu2,
                                             uint32_t kv0, uint32_t kv1, uint32_t ksv2,
                                             uint32_t one) {
    int s0  = blockIdx.x * 1024 + threadIdx.x * 4;     // 4 consecutive positions
    int b   = blockIdx.y;                              // [0, BB)
    int tid = threadIdx.x;
    __shared__ int sc[KK];
    if (tid < KK) sc[tid] = 0;
    __syncthreads();

    int4 mm = *reinterpret_cast<const int4*>(&g_msc[s0]);
    int nn[4] = { mm.x & 0xffff, mm.y & 0xffff, mm.z & 0xffff, mm.w & 0xffff };
    int cc[4] = { mm.x >> 16,    mm.y >> 16,    mm.z >> 16,    mm.w >> 16 };
    uint32_t base = (uint32_t)b * NN;

    uint32_t u[4], v[4];
    #pragma unroll
    for (int e = 0; e < 4; e++) {
        uint32_t ctr = base + (uint32_t)nn[e];
        u[e] = tf_bits32_d(ku0, ku1, ksu2, one, ctr);
        v[e] = tf_bits32_d(kv0, kv1, ksv2, one, ctr);
    }

    uint4 kb;
    unsigned kbv[4];
    #pragma unroll
    for (int e = 0; e < 4; e++) {
        float cf = (float)cc[e];
        float fu = __uint_as_float((u[e] >> 9) | 0x3f800000u) - 1.0f;
        // key = fl(c + fl(u*0.999f)) : NO fma contraction (matches XLA)
        kbv[e] = __float_as_uint(__fadd_rn(cf, __fmul_rn(fu, 0.999f)));
    }
    kb.x = kbv[0]; kb.y = kbv[1]; kb.z = kbv[2]; kb.w = kbv[3];

    size_t o0 = (size_t)b * NN + s0;
    // Within a cluster segment all keys share the integer part c, so the raw
    // float bits order identically to the float values (all nonnegative).
    *reinterpret_cast<uint4*>(&g_key[o0])  = kb;
    *reinterpret_cast<float4*>(&out[o0])   = make_float4(0.f, 0.f, 0.f, 0.f);

    #pragma unroll
    for (int e = 0; e < 4; e++) {
        // candidate push (~3.9% of elements)
        if (kbv[e] < __float_as_uint((float)cc[e] + THRF))
            push_cand(b, cc[e], s0 + e, kbv[e]);
        float fv = __uint_as_float((v[e] >> 9) | 0x3f800000u) - 1.0f;
        if (fv < g_p[cc[e]]) atomicAdd(&sc[cc[e]], 1);   // rare (~p=0.0016)
    }
    __syncthreads();
    if (tid < KK && sc[tid]) atomicAdd(&g_counts[b*KK + tid], sc[tid]);
}

// ---------------- B2: per-(b,k) warp selection of `count` smallest ---------
// Fast path: candidates = ALL segment elements with key fraction < THRF.
// If cnt <= nc <= CSLOTS, the cnt smallest of the segment are necessarily
// all candidates => selecting among candidates is exact. Otherwise fall back
// to full-scan rounds over g_key (deterministic, always correct).
// Stable argsort tie-break: counting sort is stable => position j monotone in
// original index n within a segment; composite (key_bits, j) reproduces it.
__global__ void __launch_bounds__(256) k_select(const float* __restrict__ x,
                                                float* __restrict__ out) {
    int lane = threadIdx.x & 31;
    int gwid = (blockIdx.x * blockDim.x + threadIdx.x) >> 5;
    if (gwid >= BB * KK) return;
    int b = gwid >> 6;
    int k = gwid & 63;

    int st = g_starts[k];
    int sz = g_starts[k+1] - st;
    int cnt = g_counts[b*KK + k];
    if (cnt < 1) cnt = 1;            // counts = max(counts, 1)
    if (cnt > sz) cnt = sz;

    int seg = b * KK + k;
    int nc = g_cnum[seg];

    unsigned long long prev = 0ull;  // composites are >= 1
    if (cnt <= nc && nc <= CSLOTS) {
        const unsigned long long* cand = &g_cand[(size_t)seg * CSLOTS];
        for (int r = 0; r < cnt; r++) {
            unsigned long long best = ~0ull;
            for (int j = lane; j < nc; j += 32) {
                unsigned long long cmp = __ldg(&cand[j]);
                if (cmp > prev && cmp < best) best = cmp;
            }
            #pragma unroll
            for (int o = 16; o; o >>= 1) {
                unsigned long long other = __shfl_xor_sync(0xffffffffu, best, o);
                if (other < best) best = other;
            }
            prev = best;
            if (lane == 0) {
                unsigned int j = (unsigned int)((best - 1ull) & 0xffffffffull);
                int n = g_msc[st + (int)j] & 0xffff;
                size_t idx = (size_t)b * NN + (unsigned)n;
                out[idx] = x[idx];
            }
        }
    } else {
        // fallback: full-scan rounds over the stored keys
        const unsigned int* row = g_key + (size_t)b * NN + st;
        for (int r = 0; r < cnt; r++) {
            unsigned long long best = ~0ull;
            #pragma unroll 4
            for (int j = lane; j < sz; j += 32) {
                unsigned long long cmp =
                    ((((unsigned long long)__ldg(&row[j])) << 32) | (unsigned)j) + 1ull;
                if (cmp > prev && cmp < best) best = cmp;
            }
            #pragma unroll
            for (int o = 16; o; o >>= 1) {
                unsigned long long other = __shfl_xor_sync(0xffffffffu, best, o);
                if (other < best) best = other;
            }
            if (best == ~0ull) break;
            prev = best;
            if (lane == 0) {
                unsigned int j = (unsigned int)((best - 1ull) & 0xffffffffull);
                int n = g_msc[st + (int)j] & 0xffff;
                size_t idx = (size_t)b * NN + (unsigned)n;
                out[idx] = x[idx];
            }
        }
    }
}

// ---------------- host-side threefry for the key split ---------------------
static inline uint32_t h_rotl(uint32_t x, int d) { return (x << d) | (x >> (32 - d)); }
static void h_threefry(uint32_t k0, uint32_t k1, uint32_t x0, uint32_t x1,
                       uint32_t& o0, uint32_t& o1) {
    uint32_t ks2 = k0 ^ k1 ^ 0x1BD11BDAu;
    x0 += k0; x1 += k1;
    static const int ra[4] = {13,15,26,6}, rb[4] = {17,29,16,24};
    const int* rots[5] = {ra, rb, ra, rb, ra};
    const uint32_t xi[5] = {k1, ks2, k0, k1, ks2};
    const uint32_t yi[5] = {ks2, k0, k1, ks2, k0};
    for (int g = 0; g < 5; g++) {
        for (int i = 0; i < 4; i++) {
            x0 += x1; x1 = h_rotl(x1, rots[g][i]); x1 ^= x0;
        }
        x0 += xi[g];
        x1 += yi[g] + (uint32_t)(g + 1);
    }
    o0 = x0; o1 = x1;
}

extern "C" void kernel_launch(void* const* d_in, const int* in_sizes, int n_in,
                              void* d_out, int out_size) {
    const float* x      = (const float*)d_in[0];
    const float* w      = (const float*)d_in[1];
    const int*   assign = (const int*)  d_in[2];
    float* out = (float*)d_out;
    (void)in_sizes; (void)n_in; (void)out_size;

    // jax_threefry_partitionable=True (modern default):
    //   split(key(42)) fold-like: subkey i = full cipher((0,42), (hi=0, lo=i))
    //   ku = cipher(0,42; 0,0), kv = cipher(0,42; 0,1)
    uint32_t ku0, ku1, kv0, kv1;
    h_threefry(0u, 42u, 0u, 0u, ku0, ku1);
    h_threefry(0u, 42u, 0u, 1u, kv0, kv1);
    uint32_t ksu2 = ku0 ^ ku1 ^ 0x1BD11BDAu;
    uint32_t ksv2 = kv0 ^ kv1 ^ 0x1BD11BDAu;

    k_prep_hist<<<NTILES, TILE>>>(w, assign);
    k_scan<<<1, KK>>>();
    k_scatter<<<NTILES, TILE>>>(assign);
    k_gen<<<dim3(NN/1024, BB), 256>>>(out, ku0, ku1, ksu2, kv0, kv1, ksv2, 1u);
    k_select<<<(BB*KK)/8, 256>>>(x, out);
}